// round 7
// baseline (speedup 1.0000x reference)
#include <cuda_runtime.h>
#include <cstdint>

#define RES      64
#define N_PHAL   20
#define MAX_B    256

constexpr int FLT_PER_CHUNK = RES * RES * 5;        // 20480 floats = 80 KB
constexpr int NSTAGE        = 4;                    // ring depth
constexpr int SUBS_PER_CHUNK= 8;
constexpr int SUB_FLT       = FLT_PER_CHUNK / SUBS_PER_CHUNK; // 2560 floats = 10 KB
constexpr int SUB_POS       = SUB_FLT / 5;          // 512 positions
constexpr unsigned SUB_BYTES = SUB_FLT * 4;         // 10240
constexpr int THREADS       = 256;
constexpr int GRID          = 592;                  // 148 SMs x 4 CTAs, persistent

__device__ float        g_scratch[MAX_B * N_PHAL * 5];
__device__ unsigned int g_count = 0;

__device__ __forceinline__ float warp_red(float v) {
    #pragma unroll
    for (int o = 16; o > 0; o >>= 1)
        v += __shfl_down_sync(0xffffffffu, v, o);
    return v;
}

__device__ __forceinline__ void mbar_init(unsigned int mbar, unsigned int count) {
    asm volatile("mbarrier.init.shared.b64 [%0], %1;" :: "r"(mbar), "r"(count) : "memory");
}
__device__ __forceinline__ void mbar_expect_tx(unsigned int mbar, unsigned int bytes) {
    asm volatile("mbarrier.arrive.expect_tx.shared.b64 _, [%0], %1;"
                 :: "r"(mbar), "r"(bytes) : "memory");
}
__device__ __forceinline__ void mbar_wait(unsigned int mbar, unsigned int parity) {
    unsigned int done;
    asm volatile(
        "{\n\t.reg .pred p;\n\t"
        "mbarrier.try_wait.parity.acquire.cta.shared::cta.b64 p, [%1], %2;\n\t"
        "selp.b32 %0, 1, 0, p;\n\t}"
        : "=r"(done) : "r"(mbar), "r"(parity) : "memory");
    if (!done) {
        asm volatile(
            "{\n\t.reg .pred P1;\n\t"
            "WAIT_LOOP_%=:\n\t"
            "mbarrier.try_wait.parity.acquire.cta.shared::cta.b64 P1, [%0], %1, 0x989680;\n\t"
            "@P1 bra.uni WAIT_DONE_%=;\n\t"
            "bra.uni WAIT_LOOP_%=;\n\t"
            "WAIT_DONE_%=:\n\t}"
            :: "r"(mbar), "r"(parity) : "memory");
    }
}
__device__ __forceinline__ void bulk_g2s(unsigned int dst, const void* src,
                                         unsigned int bytes, unsigned int mbar) {
    asm volatile(
        "cp.async.bulk.shared::cta.global.mbarrier::complete_tx::bytes [%0], [%1], %2, [%3];"
        :: "r"(dst), "l"(src), "r"(bytes), "r"(mbar) : "memory");
}

__global__ __launch_bounds__(THREADS, 4) void fused_kernel(
    const float* __restrict__ x, float* __restrict__ scratch,
    float* __restrict__ out, int total_chunks)
{
    __shared__ alignas(16) float buf[NSTAGE][SUB_FLT];   // 4 x 10 KB ring
    __shared__ alignas(8)  unsigned long long mbar_st[NSTAGE];
    __shared__ float red[8][7];
    __shared__ int   s_last;

    const int t    = threadIdx.x;
    const int bid  = blockIdx.x;
    const int grid = gridDim.x;

    const int nchunks  = (bid < total_chunks)
                       ? (total_chunks - bid + grid - 1) / grid : 0;
    const int n_stages = nchunks * SUBS_PER_CHUNK;

    unsigned int mb0 = (unsigned int)__cvta_generic_to_shared(&mbar_st[0]);
    unsigned int sb0 = (unsigned int)__cvta_generic_to_shared(&buf[0][0]);

    if (t == 0) {
        #pragma unroll
        for (int i = 0; i < NSTAGE; ++i) mbar_init(mb0 + i * 8, 1);
    }
    __syncthreads();

    // issue stage st: chunk = bid + (st>>3)*grid, subtile = st&7, buffer = st&3
    auto issue = [&](int st) {
        if (t == 0) {
            int ch = bid + (st >> 3) * grid;
            const float* src = x + (size_t)ch * FLT_PER_CHUNK + (st & 7) * SUB_FLT;
            int b = st & 3;
            mbar_expect_tx(mb0 + b * 8, SUB_BYTES);
            bulk_g2s(sb0 + b * (SUB_FLT * 4), src, SUB_BYTES, mb0 + b * 8);
        }
    };

    // prologue: fill the ring
    for (int p = 0; p < NSTAGE && p < n_stages; ++p) issue(p);

    float A = 0.f, Bm = 0.f, C = 0.f, D = 0.f, E = 0.f, F = 0.f, den = 0.f;

    for (int st = 0; st < n_stages; ++st) {
        const int b = st & 3;
        mbar_wait(mb0 + b * 8, (st >> 2) & 1);   // per-thread wait, acquire

        // this thread's 2 positions: 10 floats at 40B offset; 5 x LDS.64
        const float2* s2 = (const float2*)(buf[b] + t * 10);
        float2 w0 = s2[0];   // f0A f1A
        float2 w1 = s2[1];   // mA  d0A
        float2 w2 = s2[2];   // d1A f0B
        float2 w3 = s2[3];   // f1B mB
        float2 w4 = s2[4];   // d0B d1B

        int pos0 = (st & 7) * SUB_POS + t * 2;
        float fi = (float)(pos0 >> 6);           // row (2 | 64 -> same for both)
        float fj = (float)(pos0 & 63);

        // position A
        { float m = w1.x, am = fabsf(m), sc = m * am;
          float t0 = sc * w0.x, t1 = sc * w0.y;
          A  = fmaf(t1, w1.y, A);  Bm = fmaf(t0, w1.y, Bm);
          C  = fmaf(t1, w2.x, C);  D  = fmaf(t0, w2.x, D);
          E  = fmaf(am, fi, E);    F  = fmaf(am, fj, F);
          den += am; }
        // position B
        { float m = w3.y, am = fabsf(m), sc = m * am;
          float t0 = sc * w2.y, t1 = sc * w3.x;
          A  = fmaf(t1, w4.x, A);  Bm = fmaf(t0, w4.x, Bm);
          C  = fmaf(t1, w4.y, C);  D  = fmaf(t0, w4.y, D);
          E  = fmaf(am, fi, E);    F  = fmaf(am, fj + 1.f, F);
          den += am; }

        __syncthreads();               // all threads done reading buf[b]
        if (st + NSTAGE < n_stages) issue(st + NSTAGE);

        // per-chunk epilogue (ring still full -> DRAM keeps streaming)
        if ((st & 7) == 7) {
            float a = warp_red(A),  bb = warp_red(Bm), c = warp_red(C),
                  d = warp_red(D),  e = warp_red(E),  f = warp_red(F),
                  dn = warp_red(den);
            int wid = t >> 5, lane = t & 31;
            if (lane == 0) {
                red[wid][0] = a; red[wid][1] = bb; red[wid][2] = c;
                red[wid][3] = d; red[wid][4] = e;  red[wid][5] = f;
                red[wid][6] = dn;
            }
            __syncthreads();
            if (t == 0) {
                float ra = 0.f, rb = 0.f, rc = 0.f, rd = 0.f,
                      re = 0.f, rf = 0.f, rdn = 0.f;
                #pragma unroll
                for (int w = 0; w < 8; ++w) {
                    ra += red[w][0]; rb += red[w][1]; rc += red[w][2];
                    rd += red[w][3]; re += red[w][4]; rf += red[w][5];
                    rdn += red[w][6];
                }
                float inv = 1.f / ((rdn == 0.f) ? 1.f : rdn);
                int ch = bid + (st >> 3) * grid;
                float* o = scratch + (size_t)ch * 5;
                o[0] = (ra + re) * inv;   // vf0
                o[1] = (rf - rb) * inv;   // vf1
                o[2] = (re - rc) * inv;   // vs0
                o[3] = (rd + rf) * inv;   // vs1
                o[4] = rdn;
            }
            __syncthreads();              // red[] reusable next chunk
            A = Bm = C = D = E = F = den = 0.f;
        }
    }

    // ---- last block to finish assembles the (B, 21, 2) output ----
    if (t == 0) {
        __threadfence();
        unsigned int old = atomicAdd(&g_count, 1u);
        s_last = (old == (unsigned)grid - 1u) ? 1 : 0;
    }
    __syncthreads();

    if (s_last) {
        if (t == 0) g_count = 0;          // reset for next graph replay
        __threadfence();
        const int B = total_chunks / N_PHAL;
        const int total = B * 42;
        for (int o = t; o < total; o += THREADS) {
            int c = o & 1;
            int r = (o >> 1) % 21;
            int b = o / 42;
            const float* sp = scratch + (size_t)b * N_PHAL * 5;

            float val;
            if (r == 0) {
                float acc = 0.f;
                #pragma unroll
                for (int k = 0; k < 5; ++k) {
                    int p = 4 * k;
                    float dn = __ldcg(sp + p * 5 + 4);
                    float vf = __ldcg(sp + p * 5 + c);
                    acc += (dn != 0.f) ? vf : 0.f;
                }
                val = acc * 0.2f;
            } else {
                int q  = r;                  // 1..20
                int iq = (q - 1) >> 2;
                int pq = 8 * iq + 4 - q;     // 4*iq + j_q
                int jq = pq - 4 * iq;
                int pn = min(pq + 1, N_PHAL - 1);
                float vs = __ldcg(sp + pq * 5 + 2 + c);
                if (jq == 3) val = vs;
                else         val = 0.5f * (vs + __ldcg(sp + pn * 5 + c));
            }
            out[o] = val;
        }
    }
}

extern "C" void kernel_launch(void* const* d_in, const int* in_sizes, int n_in,
                              void* d_out, int out_size)
{
    const float* x = (const float*)d_in[0];
    float* out = (float*)d_out;
    int B = in_sizes[0] / (N_PHAL * RES * RES * 5);   // 256
    int total_chunks = B * N_PHAL;                    // 5120

    float* scratch;
    cudaGetSymbolAddress((void**)&scratch, g_scratch);

    int grid = (total_chunks < GRID) ? total_chunks : GRID;
    fused_kernel<<<grid, THREADS>>>(x, scratch, out, total_chunks);
}

// round 9
// speedup vs baseline: 1.0173x; 1.0173x over previous
#include <cuda_runtime.h>
#include <cstdint>

#define RES      64
#define N_PHAL   20
#define MAX_B    256

constexpr int FLT_PER_CHUNK  = RES * RES * 5;                  // 20480 floats = 80 KB
constexpr int NSTAGE         = 4;                              // ring depth
constexpr int SUBS_PER_CHUNK = 8;
constexpr int SUB_FLT        = FLT_PER_CHUNK / SUBS_PER_CHUNK; // 2560 floats = 10 KB
constexpr int SUB_POS        = SUB_FLT / 5;                    // 512 positions
constexpr unsigned SUB_BYTES = SUB_FLT * 4;                    // 10240
constexpr int THREADS        = 256;
constexpr int GRID           = 740;                            // 148 SMs x 5 CTAs

__device__ float        g_scratch[MAX_B * N_PHAL * 5];
__device__ unsigned int g_count = 0;
__device__ unsigned int g_next  = 0;    // work-stealing chunk counter

__device__ __forceinline__ float warp_red(float v) {
    #pragma unroll
    for (int o = 16; o > 0; o >>= 1)
        v += __shfl_down_sync(0xffffffffu, v, o);
    return v;
}

__device__ __forceinline__ void mbar_init(unsigned int mbar, unsigned int count) {
    asm volatile("mbarrier.init.shared.b64 [%0], %1;" :: "r"(mbar), "r"(count) : "memory");
}
__device__ __forceinline__ void mbar_expect_tx(unsigned int mbar, unsigned int bytes) {
    asm volatile("mbarrier.arrive.expect_tx.shared.b64 _, [%0], %1;"
                 :: "r"(mbar), "r"(bytes) : "memory");
}
__device__ __forceinline__ void mbar_wait(unsigned int mbar, unsigned int parity) {
    unsigned int done;
    asm volatile(
        "{\n\t.reg .pred p;\n\t"
        "mbarrier.try_wait.parity.acquire.cta.shared::cta.b64 p, [%1], %2;\n\t"
        "selp.b32 %0, 1, 0, p;\n\t}"
        : "=r"(done) : "r"(mbar), "r"(parity) : "memory");
    if (!done) {
        asm volatile(
            "{\n\t.reg .pred P1;\n\t"
            "WAIT_LOOP_%=:\n\t"
            "mbarrier.try_wait.parity.acquire.cta.shared::cta.b64 P1, [%0], %1, 0x989680;\n\t"
            "@P1 bra.uni WAIT_DONE_%=;\n\t"
            "bra.uni WAIT_LOOP_%=;\n\t"
            "WAIT_DONE_%=:\n\t}"
            :: "r"(mbar), "r"(parity) : "memory");
    }
}
__device__ __forceinline__ void bulk_g2s(unsigned int dst, const void* src,
                                         unsigned int bytes, unsigned int mbar) {
    asm volatile(
        "cp.async.bulk.shared::cta.global.mbarrier::complete_tx::bytes [%0], [%1], %2, [%3];"
        :: "r"(dst), "l"(src), "r"(bytes), "r"(mbar) : "memory");
}

__global__ __launch_bounds__(THREADS, 5) void fused_kernel(
    const float* __restrict__ x, float* __restrict__ scratch,
    float* __restrict__ out, int total_chunks)
{
    __shared__ alignas(16) float buf[NSTAGE][SUB_FLT];   // 4 x 10 KB ring
    __shared__ alignas(8)  unsigned long long mbar_st[NSTAGE];
    __shared__ float red[8][7];
    __shared__ int   chunks_sm[2];        // double-buffered stolen chunk ids
    __shared__ int   s_last;

    const int t    = threadIdx.x;
    const int grid = gridDim.x;

    unsigned int mb0 = (unsigned int)__cvta_generic_to_shared(&mbar_st[0]);
    unsigned int sb0 = (unsigned int)__cvta_generic_to_shared(&buf[0][0]);

    if (t == 0) {
        #pragma unroll
        for (int i = 0; i < NSTAGE; ++i) mbar_init(mb0 + i * 8, 1);
        unsigned int id = atomicAdd(&g_next, 1u);           // first chunk
        chunks_sm[0] = (id < (unsigned)total_chunks) ? (int)id : -1;
        chunks_sm[1] = -1;
    }
    __syncthreads();

    // ---- prologue: stages 0..3 (all within chunk slot 0) ----
    if (t == 0 && chunks_sm[0] >= 0) {
        const float* cb = x + (size_t)chunks_sm[0] * FLT_PER_CHUNK;
        #pragma unroll
        for (int p = 0; p < NSTAGE; ++p) {
            mbar_expect_tx(mb0 + p * 8, SUB_BYTES);
            bulk_g2s(sb0 + p * (SUB_FLT * 4), cb + p * SUB_FLT,
                     SUB_BYTES, mb0 + p * 8);
        }
    }

    float A = 0.f, Bm = 0.f, C = 0.f, D = 0.f, E = 0.f, F = 0.f, den = 0.f;

    for (int st = 0; ; ++st) {
        const int slot = (st >> 3) & 1;
        const int ch   = chunks_sm[slot];     // safe: >=1 __syncthreads since write
        if (ch < 0) break;

        const int b = st & 3;
        mbar_wait(mb0 + b * 8, (st >> 2) & 1);

        // this thread's 2 positions: 10 floats at 40B offset; 5 x LDS.64
        const float2* s2 = (const float2*)(buf[b] + t * 10);
        float2 w0 = s2[0];   // f0A f1A
        float2 w1 = s2[1];   // mA  d0A
        float2 w2 = s2[2];   // d1A f0B
        float2 w3 = s2[3];   // f1B mB
        float2 w4 = s2[4];   // d0B d1B

        int pos0 = (st & 7) * SUB_POS + t * 2;
        float fi = (float)(pos0 >> 6);        // row (2 | 64 -> same for both)
        float fj = (float)(pos0 & 63);

        // position A
        { float m = w1.x, am = fabsf(m), sc = m * am;
          float t0 = sc * w0.x, t1 = sc * w0.y;
          A  = fmaf(t1, w1.y, A);  Bm = fmaf(t0, w1.y, Bm);
          C  = fmaf(t1, w2.x, C);  D  = fmaf(t0, w2.x, D);
          E  = fmaf(am, fi, E);    F  = fmaf(am, fj, F);
          den += am; }
        // position B
        { float m = w3.y, am = fabsf(m), sc = m * am;
          float t0 = sc * w2.y, t1 = sc * w3.x;
          A  = fmaf(t1, w4.x, A);  Bm = fmaf(t0, w4.x, Bm);
          C  = fmaf(t1, w4.y, C);  D  = fmaf(t0, w4.y, D);
          E  = fmaf(am, fi, E);    F  = fmaf(am, fj + 1.f, F);
          den += am; }

        __syncthreads();                      // all threads done reading buf[b]

        // ---- t0: steal next chunk at prefetch horizon + issue stage st+4 ----
        if (t == 0) {
            int st2 = st + NSTAGE;
            int sl2 = (st2 >> 3) & 1;
            if ((st2 & 7) == 0) {             // entering a new local chunk: steal
                unsigned int id = atomicAdd(&g_next, 1u);
                chunks_sm[sl2] = (id < (unsigned)total_chunks) ? (int)id : -1;
            }
            int ch2 = chunks_sm[sl2];
            if (ch2 >= 0) {
                int b2 = st2 & 3;
                const float* src = x + (size_t)ch2 * FLT_PER_CHUNK
                                     + (st2 & 7) * SUB_FLT;
                mbar_expect_tx(mb0 + b2 * 8, SUB_BYTES);
                bulk_g2s(sb0 + b2 * (SUB_FLT * 4), src, SUB_BYTES, mb0 + b2 * 8);
            }
        }

        // ---- per-chunk epilogue (ring still streaming) ----
        if ((st & 7) == 7) {
            float a = warp_red(A),  bb = warp_red(Bm), c = warp_red(C),
                  d = warp_red(D),  e = warp_red(E),  f = warp_red(F),
                  dn = warp_red(den);
            int wid = t >> 5, lane = t & 31;
            if (lane == 0) {
                red[wid][0] = a; red[wid][1] = bb; red[wid][2] = c;
                red[wid][3] = d; red[wid][4] = e;  red[wid][5] = f;
                red[wid][6] = dn;
            }
            __syncthreads();
            if (t == 0) {
                float ra = 0.f, rb = 0.f, rc = 0.f, rd = 0.f,
                      re = 0.f, rf = 0.f, rdn = 0.f;
                #pragma unroll
                for (int w = 0; w < 8; ++w) {
                    ra += red[w][0]; rb += red[w][1]; rc += red[w][2];
                    rd += red[w][3]; re += red[w][4]; rf += red[w][5];
                    rdn += red[w][6];
                }
                float inv = 1.f / ((rdn == 0.f) ? 1.f : rdn);
                float* o = scratch + (size_t)ch * 5;
                o[0] = (ra + re) * inv;   // vf0
                o[1] = (rf - rb) * inv;   // vf1
                o[2] = (re - rc) * inv;   // vs0
                o[3] = (rd + rf) * inv;   // vs1
                o[4] = rdn;
            }
            __syncthreads();              // red[] reusable next chunk
            A = Bm = C = D = E = F = den = 0.f;
        }
    }

    // ---- last CTA to finish assembles the (B, 21, 2) output ----
    if (t == 0) {
        __threadfence();
        unsigned int old = atomicAdd(&g_count, 1u);
        s_last = (old == (unsigned)grid - 1u) ? 1 : 0;
    }
    __syncthreads();

    if (s_last) {
        if (t == 0) { g_count = 0; g_next = 0; }   // reset for graph replay
        __threadfence();
        const int B = total_chunks / N_PHAL;
        const int total = B * 42;
        for (int o = t; o < total; o += THREADS) {
            int c = o & 1;
            int r = (o >> 1) % 21;
            int b = o / 42;
            const float* sp = scratch + (size_t)b * N_PHAL * 5;

            float val;
            if (r == 0) {
                float acc = 0.f;
                #pragma unroll
                for (int k = 0; k < 5; ++k) {
                    int p = 4 * k;
                    float dn = __ldcg(sp + p * 5 + 4);
                    float vf = __ldcg(sp + p * 5 + c);
                    acc += (dn != 0.f) ? vf : 0.f;
                }
                val = acc * 0.2f;
            } else {
                int q  = r;                  // 1..20
                int iq = (q - 1) >> 2;
                int pq = 8 * iq + 4 - q;     // 4*iq + j_q
                int jq = pq - 4 * iq;
                int pn = min(pq + 1, N_PHAL - 1);
                float vs = __ldcg(sp + pq * 5 + 2 + c);
                if (jq == 3) val = vs;
                else         val = 0.5f * (vs + __ldcg(sp + pn * 5 + c));
            }
            out[o] = val;
        }
    }
}

extern "C" void kernel_launch(void* const* d_in, const int* in_sizes, int n_in,
                              void* d_out, int out_size)
{
    const float* x = (const float*)d_in[0];
    float* out = (float*)d_out;
    int B = in_sizes[0] / (N_PHAL * RES * RES * 5);   // 256
    int total_chunks = B * N_PHAL;                    // 5120

    float* scratch;
    cudaGetSymbolAddress((void**)&scratch, g_scratch);

    int grid = (total_chunks < GRID) ? total_chunks : GRID;
    fused_kernel<<<grid, THREADS>>>(x, scratch, out, total_chunks);
}